// round 1
// baseline (speedup 1.0000x reference)
#include <cuda_runtime.h>
#include <cstdint>

#define NIR 10
#define EPS2 1e-12f
#define INV_SQRT10 0.31622776601683794f

static __device__ __forceinline__ float ex2f(float x){ float r; asm("ex2.approx.f32 %0, %1;" : "=f"(r) : "f"(x)); return r; }
static __device__ __forceinline__ float rcpf(float x){ float r; asm("rcp.approx.f32 %0, %1;" : "=f"(r) : "f"(x)); return r; }
static __device__ __forceinline__ float rsqf(float x){ float r; asm("rsqrt.approx.f32 %0, %1;" : "=f"(r) : "f"(x)); return r; }

// tanh(z) = 1 - 2/(1+exp(2z)); robust for all z (inf/0 saturate correctly)
static __device__ __forceinline__ float tanh_fast(float z){
    float e = ex2f(z * 2.8853900817779268f);   // 2*log2(e)
    float r = rcpf(e + 1.0f);
    return fmaf(-2.0f, r, 1.0f);
}

static __device__ __forceinline__ uint64_t pack2(float lo, float hi){
    uint64_t r; asm("mov.b64 %0, {%1, %2};" : "=l"(r) : "f"(lo), "f"(hi)); return r;
}
static __device__ __forceinline__ float2 unpack2(uint64_t v){
    float2 f; asm("mov.b64 {%0, %1}, %2;" : "=f"(f.x), "=f"(f.y) : "l"(v)); return f;
}
static __device__ __forceinline__ uint64_t fma2(uint64_t a, uint64_t b, uint64_t c){
    uint64_t d; asm("fma.rn.f32x2 %0, %1, %2, %3;" : "=l"(d) : "l"(a), "l"(b), "l"(c)); return d;
}

__global__ __launch_bounds__(256) void trq_2b_kernel(
    const float* __restrict__ v1b,   // (B,3)
    const float* __restrict__ invar, // (B,P,2)
    const float* __restrict__ vec2,  // (B,P,6)
    const float* __restrict__ W1,    // (2,10)
    const float* __restrict__ b1,    // (10)
    const float* __restrict__ W2,    // (10,10)
    const float* __restrict__ b2,    // (10)
    const float* __restrict__ lw1,   // (1,10)
    const float* __restrict__ nb1,   // (10)
    const float* __restrict__ lw2,   // (10,10)
    const float* __restrict__ nb2,   // (10)
    const float* __restrict__ wf,    // (10)
    float* __restrict__ out)         // (B,3)
{
    __shared__ float sW1[2][NIR];
    __shared__ float sB1[NIR], sB2[NIR], sA[NIR], sNB1[NIR], sNB2[NIR], sWFS[NIR];
    __shared__ __align__(8) float sW2[NIR][NIR];    // W2[u][v]
    __shared__ __align__(8) float sLW2[NIR][NIR];   // lw1[u]*lw2[u][v]/sqrt(10)
    __shared__ float red[3][32];

    const int tid = threadIdx.x;
    if (tid < 100){
        int u = tid / 10, v = tid % 10;
        sW2[u][v]  = W2[tid];
        sLW2[u][v] = lw1[u] * lw2[tid] * INV_SQRT10;
    }
    if (tid < 20) sW1[tid/10][tid%10] = W1[tid];
    if (tid < 10){
        sB1[tid]  = b1[tid];
        sB2[tid]  = b2[tid];
        sNB1[tid] = nb1[tid];
        sNB2[tid] = nb2[tid];
        sWFS[tid] = wf[tid] * INV_SQRT10;
        float l = lw1[tid];
        sA[tid] = l * l;
    }
    __syncthreads();

    const int b = blockIdx.x;
    const size_t e = (size_t)b * blockDim.x + tid;

    // ---- loads ----
    const float2 iv = reinterpret_cast<const float2*>(invar)[e];
    const float* vp = vec2 + e * 6;
    const float vx = vp[3], vy = vp[4], vz = vp[5];

    // ---- y1 = relu(invar @ W1 + b1) ----
    float y1[NIR];
    #pragma unroll
    for (int u = 0; u < NIR; u++)
        y1[u] = fmaxf(fmaf(iv.x, sW1[0][u], fmaf(iv.y, sW1[1][u], sB1[u])), 0.0f);

    // ---- y2 = relu(y1 @ W2 + b2), paired f32x2 over v ----
    uint64_t y1d[NIR];
    #pragma unroll
    for (int u = 0; u < NIR; u++) y1d[u] = pack2(y1[u], y1[u]);

    float y2[NIR];
    #pragma unroll
    for (int j = 0; j < NIR/2; j++){
        uint64_t acc = pack2(sB2[2*j], sB2[2*j+1]);
        const uint64_t* wrow;
        #pragma unroll
        for (int u = 0; u < NIR; u++){
            wrow = reinterpret_cast<const uint64_t*>(&sW2[u][0]);
            acc = fma2(y1d[u], wrow[j], acc);
        }
        float2 r = unpack2(acc);
        y2[2*j]   = fmaxf(r.x, 0.0f);
        y2[2*j+1] = fmaxf(r.y, 0.0f);
    }

    // ---- scalar gate chain: depends only on n2 = |v|^2 ----
    const float n2 = fmaf(vx, vx, fmaf(vy, vy, vz * vz));

    // layer-1 norm activation (lw1 factor folded into sLW2)
    float g[NIR];
    #pragma unroll
    for (int u = 0; u < NIR; u++){
        float arg = fmaf(sA[u], n2, EPS2);
        float inv = rsqf(arg);
        float nrm = arg * inv;
        float th  = tanh_fast(nrm + sNB1[u]);
        g[u] = th * inv;
    }

    // c_v = sum_u g_u * (lw1_u * lw2[u][v]) / sqrt(10), paired f32x2
    uint64_t gd[NIR];
    #pragma unroll
    for (int u = 0; u < NIR; u++) gd[u] = pack2(g[u], g[u]);

    float c[NIR];
    #pragma unroll
    for (int j = 0; j < NIR/2; j++){
        uint64_t acc = 0ull;
        #pragma unroll
        for (int u = 0; u < NIR; u++){
            const uint64_t* wrow = reinterpret_cast<const uint64_t*>(&sLW2[u][0]);
            acc = fma2(gd[u], wrow[j], acc);
        }
        float2 r = unpack2(acc);
        c[2*j]   = r.x;
        c[2*j+1] = r.y;
    }

    // layer-2 norm activation + final contraction
    float S = 0.0f;
    #pragma unroll
    for (int v = 0; v < NIR; v++){
        float cv  = c[v];
        float arg = fmaf(cv * cv, n2, EPS2);
        float inv = rsqf(arg);
        float nrm = arg * inv;
        float th  = tanh_fast(nrm + sNB2[v]);
        float scal2 = th * inv;
        S = fmaf(y2[v] * cv, scal2 * sWFS[v], S);
    }

    float tx = vx * S, ty = vy * S, tz = vz * S;

    // ---- block reduction of (tx,ty,tz) ----
    #pragma unroll
    for (int off = 16; off > 0; off >>= 1){
        tx += __shfl_down_sync(0xFFFFFFFFu, tx, off);
        ty += __shfl_down_sync(0xFFFFFFFFu, ty, off);
        tz += __shfl_down_sync(0xFFFFFFFFu, tz, off);
    }
    const int wid = tid >> 5, lane = tid & 31;
    if (lane == 0){ red[0][wid] = tx; red[1][wid] = ty; red[2][wid] = tz; }
    __syncthreads();

    if (tid == 0){
        const int nw = blockDim.x >> 5;
        float sx = 0.0f, sy = 0.0f, sz = 0.0f;
        for (int w = 0; w < nw; w++){ sx += red[0][w]; sy += red[1][w]; sz += red[2][w]; }
        const float a0 = v1b[b*3+0], a1 = v1b[b*3+1], a2 = v1b[b*3+2];
        out[b*3+0] = a1 * sz - a2 * sy;
        out[b*3+1] = a2 * sx - a0 * sz;
        out[b*3+2] = a0 * sy - a1 * sx;
    }
}

extern "C" void kernel_launch(void* const* d_in, const int* in_sizes, int n_in,
                              void* d_out, int out_size)
{
    const float* v1b   = (const float*)d_in[0];
    const float* invar = (const float*)d_in[1];
    const float* vec2  = (const float*)d_in[2];
    const float* W1    = (const float*)d_in[3];
    const float* b1    = (const float*)d_in[4];
    const float* W2    = (const float*)d_in[5];
    const float* b2    = (const float*)d_in[6];
    const float* lw1   = (const float*)d_in[7];
    const float* nb1   = (const float*)d_in[8];
    const float* lw2   = (const float*)d_in[9];
    const float* nb2   = (const float*)d_in[10];
    const float* wf    = (const float*)d_in[11];

    const int B = out_size / 3;                 // 4096
    const int P = in_sizes[1] / (2 * B);        // 256

    trq_2b_kernel<<<B, P>>>(v1b, invar, vec2, W1, b1, W2, b2,
                            lw1, nb1, lw2, nb2, wf, (float*)d_out);
}